// round 2
// baseline (speedup 1.0000x reference)
#include <cuda_runtime.h>
#include <cuda_bf16.h>
#include <cstdint>

// EdgeBlock fused MLP, TF32 mma.sync path.
// x = [edges(32) | nodes[send](32) | nodes[recv](32) | globals[batch](16)]  (K=112)
// h = relu(x @ W1 + b1)   (64)
// y = h @ W2 + b2         (32)

#define TILE_M 128            // edges per CTA
#define NTHREADS 128          // 4 warps, each owns 32 edges (2 m16 tiles)

// smem float offsets
#define SX_STRIDE   116       // 112 + pad -> conflict-free fragment LDS
#define SH_STRIDE   68        // 64 + pad
#define OFF_X       0                         // 128*116 = 14848
#define OFF_W1T     14848                     // 64*116  = 7424
#define OFF_W2T     22272                     // 32*68   = 2176
#define OFF_B1      24448                     // 64
#define OFF_B2      24512                     // 32
#define OFF_IDX     24544                     // 3*128 ints (as floats)
#define SMEM_FLOATS 24928
#define SMEM_BYTES  (SMEM_FLOATS * 4)

__device__ __forceinline__ float tf32_rna(float x) {
    unsigned u;
    asm("cvt.rna.tf32.f32 %0, %1;" : "=r"(u) : "f"(x));
    return __uint_as_float(u);
}

__device__ __forceinline__ void mma_tf32_16x8x8(float* c, const unsigned* a,
                                                unsigned b0, unsigned b1) {
    asm volatile(
        "mma.sync.aligned.m16n8k8.row.col.f32.tf32.tf32.f32 "
        "{%0,%1,%2,%3}, {%4,%5,%6,%7}, {%8,%9}, {%0,%1,%2,%3};"
        : "+f"(c[0]), "+f"(c[1]), "+f"(c[2]), "+f"(c[3])
        : "r"(a[0]), "r"(a[1]), "r"(a[2]), "r"(a[3]), "r"(b0), "r"(b1));
}

__global__ void __launch_bounds__(NTHREADS, 2)
edgeblock_kernel(const float* __restrict__ nodes,
                 const float* __restrict__ edges,
                 const float* __restrict__ graph_globals,
                 const int*   __restrict__ send,
                 const int*   __restrict__ recv,
                 const int*   __restrict__ batch_edges,
                 const float* __restrict__ W1,
                 const float* __restrict__ b1,
                 const float* __restrict__ W2,
                 const float* __restrict__ b2,
                 float*       __restrict__ out) {
    extern __shared__ float sm[];
    float* sX   = sm + OFF_X;      // [128][116] tf32 (aliased by sH later)
    float* sW1T = sm + OFF_W1T;    // [n=64][k..116] tf32, W1T[n][k] = W1[k][n]
    float* sW2T = sm + OFF_W2T;    // [n=32][k..68] tf32
    float* sB1  = sm + OFF_B1;
    float* sB2  = sm + OFF_B2;
    int*   sIdx = (int*)(sm + OFF_IDX);   // send[128] | recv[128] | batch[128]

    const int t  = threadIdx.x;
    const int e0 = blockIdx.x * TILE_M;

    // ---- stage indices ----
    {
        int e = e0 + t;
        sIdx[t]       = send[e];
        sIdx[128 + t] = recv[e];
        sIdx[256 + t] = batch_edges[e];
    }
    // ---- stage weights (transposed, tf32) ----
    for (int i = t; i < 112 * 64; i += NTHREADS) {
        int k = i >> 6, n = i & 63;
        sW1T[n * SX_STRIDE + k] = tf32_rna(W1[i]);
    }
    for (int i = t; i < 64 * 32; i += NTHREADS) {
        int k = i >> 5, n = i & 31;
        sW2T[n * SH_STRIDE + k] = tf32_rna(W2[i]);
    }
    if (t < 64) sB1[t] = b1[t];
    if (t < 32) sB2[t] = b2[t];
    __syncthreads();

    // ---- stage x tile (coalesced float4 reads, tf32 convert) ----
    // edge features: 128 edges * 8 float4
    for (int i = t; i < TILE_M * 8; i += NTHREADS) {
        int e = i >> 3, seg = i & 7;
        float4 v = *reinterpret_cast<const float4*>(edges + (size_t)(e0 + e) * 32 + seg * 4);
        float* d = sX + e * SX_STRIDE + seg * 4;
        d[0] = tf32_rna(v.x); d[1] = tf32_rna(v.y);
        d[2] = tf32_rna(v.z); d[3] = tf32_rna(v.w);
    }
    // src gather
    for (int i = t; i < TILE_M * 8; i += NTHREADS) {
        int e = i >> 3, seg = i & 7;
        int n = sIdx[e];
        float4 v = *reinterpret_cast<const float4*>(nodes + (size_t)n * 32 + seg * 4);
        float* d = sX + e * SX_STRIDE + 32 + seg * 4;
        d[0] = tf32_rna(v.x); d[1] = tf32_rna(v.y);
        d[2] = tf32_rna(v.z); d[3] = tf32_rna(v.w);
    }
    // dst gather
    for (int i = t; i < TILE_M * 8; i += NTHREADS) {
        int e = i >> 3, seg = i & 7;
        int n = sIdx[128 + e];
        float4 v = *reinterpret_cast<const float4*>(nodes + (size_t)n * 32 + seg * 4);
        float* d = sX + e * SX_STRIDE + 64 + seg * 4;
        d[0] = tf32_rna(v.x); d[1] = tf32_rna(v.y);
        d[2] = tf32_rna(v.z); d[3] = tf32_rna(v.w);
    }
    // globals gather: 128 edges * 4 float4
    for (int i = t; i < TILE_M * 4; i += NTHREADS) {
        int e = i >> 2, seg = i & 3;
        int g = sIdx[256 + e];
        float4 v = *reinterpret_cast<const float4*>(graph_globals + (size_t)g * 16 + seg * 4);
        float* d = sX + e * SX_STRIDE + 96 + seg * 4;
        d[0] = tf32_rna(v.x); d[1] = tf32_rna(v.y);
        d[2] = tf32_rna(v.z); d[3] = tf32_rna(v.w);
    }
    __syncthreads();

    // ---- layer 1: [128,112] @ [112,64] ----
    const int lane = t & 31;
    const int w    = t >> 5;      // warp id: owns edges [w*32, w*32+32)
    const int g    = lane >> 2;   // groupID
    const int c    = lane & 3;    // threadID_in_group

    float acc[2][8][4];
#pragma unroll
    for (int mt = 0; mt < 2; mt++)
#pragma unroll
        for (int nt = 0; nt < 8; nt++)
#pragma unroll
            for (int q = 0; q < 4; q++) acc[mt][nt][q] = 0.0f;

#pragma unroll
    for (int ks = 0; ks < 14; ks++) {
        const int k = ks * 8;
        unsigned a[2][4];
#pragma unroll
        for (int mt = 0; mt < 2; mt++) {
            int r = w * 32 + mt * 16 + g;
            a[mt][0] = __float_as_uint(sX[r * SX_STRIDE + k + c]);
            a[mt][1] = __float_as_uint(sX[(r + 8) * SX_STRIDE + k + c]);
            a[mt][2] = __float_as_uint(sX[r * SX_STRIDE + k + c + 4]);
            a[mt][3] = __float_as_uint(sX[(r + 8) * SX_STRIDE + k + c + 4]);
        }
#pragma unroll
        for (int nt = 0; nt < 8; nt++) {
            unsigned bb0 = __float_as_uint(sW1T[(nt * 8 + g) * SX_STRIDE + k + c]);
            unsigned bb1 = __float_as_uint(sW1T[(nt * 8 + g) * SX_STRIDE + k + c + 4]);
            mma_tf32_16x8x8(acc[0][nt], a[0], bb0, bb1);
            mma_tf32_16x8x8(acc[1][nt], a[1], bb0, bb1);
        }
    }
    __syncthreads();   // everyone done reading sX; sH aliases it

    // ---- bias + relu + tf32, write h to smem ----
    float* sH = sm + OFF_X;       // [128][68]
#pragma unroll
    for (int mt = 0; mt < 2; mt++) {
        int r = w * 32 + mt * 16 + g;
#pragma unroll
        for (int nt = 0; nt < 8; nt++) {
            int col = nt * 8 + 2 * c;
            float bb0 = sB1[col], bb1 = sB1[col + 1];
            float h0 = fmaxf(acc[mt][nt][0] + bb0, 0.0f);
            float h1 = fmaxf(acc[mt][nt][1] + bb1, 0.0f);
            float h2 = fmaxf(acc[mt][nt][2] + bb0, 0.0f);
            float h3 = fmaxf(acc[mt][nt][3] + bb1, 0.0f);
            sH[r * SH_STRIDE + col]           = tf32_rna(h0);
            sH[r * SH_STRIDE + col + 1]       = tf32_rna(h1);
            sH[(r + 8) * SH_STRIDE + col]     = tf32_rna(h2);
            sH[(r + 8) * SH_STRIDE + col + 1] = tf32_rna(h3);
        }
    }
    __syncthreads();

    // ---- layer 2: [128,64] @ [64,32] ----
    float d2[2][4][4];
#pragma unroll
    for (int mt = 0; mt < 2; mt++)
#pragma unroll
        for (int nt = 0; nt < 4; nt++)
#pragma unroll
            for (int q = 0; q < 4; q++) d2[mt][nt][q] = 0.0f;

#pragma unroll
    for (int ks = 0; ks < 8; ks++) {
        const int k = ks * 8;
        unsigned a[2][4];
#pragma unroll
        for (int mt = 0; mt < 2; mt++) {
            int r = w * 32 + mt * 16 + g;
            a[mt][0] = __float_as_uint(sH[r * SH_STRIDE + k + c]);
            a[mt][1] = __float_as_uint(sH[(r + 8) * SH_STRIDE + k + c]);
            a[mt][2] = __float_as_uint(sH[r * SH_STRIDE + k + c + 4]);
            a[mt][3] = __float_as_uint(sH[(r + 8) * SH_STRIDE + k + c + 4]);
        }
#pragma unroll
        for (int nt = 0; nt < 4; nt++) {
            unsigned bb0 = __float_as_uint(sW2T[(nt * 8 + g) * SH_STRIDE + k + c]);
            unsigned bb1 = __float_as_uint(sW2T[(nt * 8 + g) * SH_STRIDE + k + c + 4]);
            mma_tf32_16x8x8(d2[0][nt], a[0], bb0, bb1);
            mma_tf32_16x8x8(d2[1][nt], a[1], bb0, bb1);
        }
    }

    // ---- epilogue: bias, write out [E,32] ----
#pragma unroll
    for (int mt = 0; mt < 2; mt++) {
        int r = w * 32 + mt * 16 + g;
#pragma unroll
        for (int nt = 0; nt < 4; nt++) {
            int col = nt * 8 + 2 * c;
            float bb0 = sB2[col], bb1 = sB2[col + 1];
            float2 v0 = make_float2(d2[mt][nt][0] + bb0, d2[mt][nt][1] + bb1);
            float2 v1 = make_float2(d2[mt][nt][2] + bb0, d2[mt][nt][3] + bb1);
            *reinterpret_cast<float2*>(out + (size_t)(e0 + r) * 32 + col)       = v0;
            *reinterpret_cast<float2*>(out + (size_t)(e0 + r + 8) * 32 + col)   = v1;
        }
    }
}

extern "C" void kernel_launch(void* const* d_in, const int* in_sizes, int n_in,
                              void* d_out, int out_size) {
    const float* nodes         = (const float*)d_in[0];
    const float* edges         = (const float*)d_in[1];
    const float* graph_globals = (const float*)d_in[2];
    const int*   send          = (const int*)d_in[3];
    const int*   recv          = (const int*)d_in[4];
    const int*   batch_edges   = (const int*)d_in[5];
    const float* W1            = (const float*)d_in[6];
    const float* b1            = (const float*)d_in[7];
    const float* W2            = (const float*)d_in[8];
    const float* b2            = (const float*)d_in[9];
    float*       out           = (float*)d_out;

    const int n_edges = in_sizes[1] / 32;          // E = 1,600,000
    const int grid    = (n_edges + TILE_M - 1) / TILE_M;

    cudaFuncSetAttribute(edgeblock_kernel,
                         cudaFuncAttributeMaxDynamicSharedMemorySize, SMEM_BYTES);
    edgeblock_kernel<<<grid, NTHREADS, SMEM_BYTES>>>(
        nodes, edges, graph_globals, send, recv, batch_edges,
        W1, b1, W2, b2, out);
}

// round 4
// speedup vs baseline: 1.5020x; 1.5020x over previous
#include <cuda_runtime.h>
#include <cuda_bf16.h>
#include <cstdint>

// EdgeBlock fused MLP, TF32 mma.sync path. Round 2: 8 warps/CTA, 16 edges/warp.
// x = [edges(32) | nodes[send](32) | nodes[recv](32) | globals[batch](16)]  (K=112)
// h = relu(x @ W1 + b1)   (64)
// y = h @ W2 + b2         (32)

#define TILE_M 128            // edges per CTA
#define NTHREADS 256          // 8 warps, each owns 16 edges (one m16 tile)

// smem float offsets
#define SX_STRIDE   116       // 112 + pad -> conflict-free fragment LDS
#define SH_STRIDE   68        // 64 + pad
#define OFF_X       0                         // 128*116 = 14848
#define OFF_W1T     14848                     // 64*116  = 7424
#define OFF_W2T     22272                     // 32*68   = 2176
#define OFF_B1      24448                     // 64
#define OFF_B2      24512                     // 32
#define OFF_IDX     24544                     // 3*128 ints (as floats)
#define SMEM_FLOATS 24928
#define SMEM_BYTES  (SMEM_FLOATS * 4)

__device__ __forceinline__ float tf32_rna(float x) {
    unsigned u;
    asm("cvt.rna.tf32.f32 %0, %1;" : "=r"(u) : "f"(x));
    return __uint_as_float(u);
}

__device__ __forceinline__ void mma_tf32_16x8x8(float* c, const unsigned* a,
                                                unsigned b0, unsigned b1) {
    asm volatile(
        "mma.sync.aligned.m16n8k8.row.col.f32.tf32.tf32.f32 "
        "{%0,%1,%2,%3}, {%4,%5,%6,%7}, {%8,%9}, {%0,%1,%2,%3};"
        : "+f"(c[0]), "+f"(c[1]), "+f"(c[2]), "+f"(c[3])
        : "r"(a[0]), "r"(a[1]), "r"(a[2]), "r"(a[3]), "r"(b0), "r"(b1));
}

__global__ void __launch_bounds__(NTHREADS, 2)
edgeblock_kernel(const float* __restrict__ nodes,
                 const float* __restrict__ edges,
                 const float* __restrict__ graph_globals,
                 const int*   __restrict__ send,
                 const int*   __restrict__ recv,
                 const int*   __restrict__ batch_edges,
                 const float* __restrict__ W1,
                 const float* __restrict__ b1,
                 const float* __restrict__ W2,
                 const float* __restrict__ b2,
                 float*       __restrict__ out) {
    extern __shared__ float sm[];
    float* sX   = sm + OFF_X;      // [128][116] tf32 (aliased by sH later)
    float* sW1T = sm + OFF_W1T;    // [n=64][k..116] tf32, W1T[n][k] = W1[k][n]
    float* sW2T = sm + OFF_W2T;    // [n=32][k..68] tf32
    float* sB1  = sm + OFF_B1;
    float* sB2  = sm + OFF_B2;
    int*   sIdx = (int*)(sm + OFF_IDX);   // send[128] | recv[128] | batch[128]

    const int t  = threadIdx.x;
    const int e0 = blockIdx.x * TILE_M;

    // ---- stage indices ----
    if (t < 128) {
        int e = e0 + t;
        sIdx[t]       = send[e];
        sIdx[128 + t] = recv[e];
        sIdx[256 + t] = batch_edges[e];
    }
    // ---- stage weights (transposed, tf32) ----
    for (int i = t; i < 112 * 64; i += NTHREADS) {
        int k = i >> 6, n = i & 63;
        sW1T[n * SX_STRIDE + k] = tf32_rna(W1[i]);
    }
    for (int i = t; i < 64 * 32; i += NTHREADS) {
        int k = i >> 5, n = i & 31;
        sW2T[n * SH_STRIDE + k] = tf32_rna(W2[i]);
    }
    if (t >= 128 && t < 192) sB1[t - 128] = b1[t - 128];
    if (t >= 192 && t < 224) sB2[t - 192] = b2[t - 192];
    __syncthreads();

    // ---- stage x tile (coalesced float4 reads, tf32 convert) ----
    // edge features: 128 edges * 8 float4
    for (int i = t; i < TILE_M * 8; i += NTHREADS) {
        int e = i >> 3, seg = i & 7;
        float4 v = *reinterpret_cast<const float4*>(edges + (size_t)(e0 + e) * 32 + seg * 4);
        float* d = sX + e * SX_STRIDE + seg * 4;
        d[0] = tf32_rna(v.x); d[1] = tf32_rna(v.y);
        d[2] = tf32_rna(v.z); d[3] = tf32_rna(v.w);
    }
    // src gather
    for (int i = t; i < TILE_M * 8; i += NTHREADS) {
        int e = i >> 3, seg = i & 7;
        int n = sIdx[e];
        float4 v = *reinterpret_cast<const float4*>(nodes + (size_t)n * 32 + seg * 4);
        float* d = sX + e * SX_STRIDE + 32 + seg * 4;
        d[0] = tf32_rna(v.x); d[1] = tf32_rna(v.y);
        d[2] = tf32_rna(v.z); d[3] = tf32_rna(v.w);
    }
    // dst gather
    for (int i = t; i < TILE_M * 8; i += NTHREADS) {
        int e = i >> 3, seg = i & 7;
        int n = sIdx[128 + e];
        float4 v = *reinterpret_cast<const float4*>(nodes + (size_t)n * 32 + seg * 4);
        float* d = sX + e * SX_STRIDE + 64 + seg * 4;
        d[0] = tf32_rna(v.x); d[1] = tf32_rna(v.y);
        d[2] = tf32_rna(v.z); d[3] = tf32_rna(v.w);
    }
    // globals gather: 128 edges * 4 float4
    for (int i = t; i < TILE_M * 4; i += NTHREADS) {
        int e = i >> 2, seg = i & 3;
        int g = sIdx[256 + e];
        float4 v = *reinterpret_cast<const float4*>(graph_globals + (size_t)g * 16 + seg * 4);
        float* d = sX + e * SX_STRIDE + 96 + seg * 4;
        d[0] = tf32_rna(v.x); d[1] = tf32_rna(v.y);
        d[2] = tf32_rna(v.z); d[3] = tf32_rna(v.w);
    }
    __syncthreads();

    // ---- layer 1: [128,112] @ [112,64]; warp w owns rows [w*16, w*16+16) ----
    const int lane = t & 31;
    const int w    = t >> 5;      // warp id 0..7
    const int g    = lane >> 2;   // groupID
    const int c    = lane & 3;    // threadID_in_group
    const int r    = w * 16 + g;  // this thread's base row

    float acc[8][4];
#pragma unroll
    for (int nt = 0; nt < 8; nt++)
#pragma unroll
        for (int q = 0; q < 4; q++) acc[nt][q] = 0.0f;

#pragma unroll
    for (int ks = 0; ks < 14; ks++) {
        const int k = ks * 8;
        unsigned a[4];
        a[0] = __float_as_uint(sX[r * SX_STRIDE + k + c]);
        a[1] = __float_as_uint(sX[(r + 8) * SX_STRIDE + k + c]);
        a[2] = __float_as_uint(sX[r * SX_STRIDE + k + c + 4]);
        a[3] = __float_as_uint(sX[(r + 8) * SX_STRIDE + k + c + 4]);
#pragma unroll
        for (int nt = 0; nt < 8; nt++) {
            unsigned bb0 = __float_as_uint(sW1T[(nt * 8 + g) * SX_STRIDE + k + c]);
            unsigned bb1 = __float_as_uint(sW1T[(nt * 8 + g) * SX_STRIDE + k + c + 4]);
            mma_tf32_16x8x8(acc[nt], a, bb0, bb1);
        }
    }
    __syncthreads();   // everyone done reading sX; sH aliases it

    // ---- bias + relu + tf32, write h to smem ----
    float* sH = sm + OFF_X;       // [128][68]
#pragma unroll
    for (int nt = 0; nt < 8; nt++) {
        int col = nt * 8 + 2 * c;
        float bb0 = sB1[col], bb1 = sB1[col + 1];
        float h0 = fmaxf(acc[nt][0] + bb0, 0.0f);
        float h1 = fmaxf(acc[nt][1] + bb1, 0.0f);
        float h2 = fmaxf(acc[nt][2] + bb0, 0.0f);
        float h3 = fmaxf(acc[nt][3] + bb1, 0.0f);
        sH[r * SH_STRIDE + col]           = tf32_rna(h0);
        sH[r * SH_STRIDE + col + 1]       = tf32_rna(h1);
        sH[(r + 8) * SH_STRIDE + col]     = tf32_rna(h2);
        sH[(r + 8) * SH_STRIDE + col + 1] = tf32_rna(h3);
    }
    __syncthreads();

    // ---- layer 2: [128,64] @ [64,32] ----
    float d2[4][4];
#pragma unroll
    for (int nt = 0; nt < 4; nt++)
#pragma unroll
        for (int q = 0; q < 4; q++) d2[nt][q] = 0.0f;

#pragma unroll
    for (int ks = 0; ks < 8; ks++) {
        const int k = ks * 8;
        unsigned a[4];
        a[0] = __float_as_uint(sH[r * SH_STRIDE + k + c]);
        a[1] = __float_as_uint(sH[(r + 8) * SH_STRIDE + k + c]);
        a[2] = __float_as_uint(sH[r * SH_STRIDE + k + c + 4]);
        a[3] = __float_as_uint(sH[(r + 8) * SH_STRIDE + k + c + 4]);
#pragma unroll
        for (int nt = 0; nt < 4; nt++) {
            unsigned bb0 = __float_as_uint(sW2T[(nt * 8 + g) * SH_STRIDE + k + c]);
            unsigned bb1 = __float_as_uint(sW2T[(nt * 8 + g) * SH_STRIDE + k + c + 4]);
            mma_tf32_16x8x8(d2[nt], a, bb0, bb1);
        }
    }

    // ---- epilogue: bias, write out [E,32] ----
#pragma unroll
    for (int nt = 0; nt < 4; nt++) {
        int col = nt * 8 + 2 * c;
        float bb0 = sB2[col], bb1 = sB2[col + 1];
        float2 v0 = make_float2(d2[nt][0] + bb0, d2[nt][1] + bb1);
        float2 v1 = make_float2(d2[nt][2] + bb0, d2[nt][3] + bb1);
        *reinterpret_cast<float2*>(out + (size_t)(e0 + r) * 32 + col)       = v0;
        *reinterpret_cast<float2*>(out + (size_t)(e0 + r + 8) * 32 + col)   = v1;
    }
}

extern "C" void kernel_launch(void* const* d_in, const int* in_sizes, int n_in,
                              void* d_out, int out_size) {
    const float* nodes         = (const float*)d_in[0];
    const float* edges         = (const float*)d_in[1];
    const float* graph_globals = (const float*)d_in[2];
    const int*   send          = (const int*)d_in[3];
    const int*   recv          = (const int*)d_in[4];
    const int*   batch_edges   = (const int*)d_in[5];
    const float* W1            = (const float*)d_in[6];
    const float* b1            = (const float*)d_in[7];
    const float* W2            = (const float*)d_in[8];
    const float* b2            = (const float*)d_in[9];
    float*       out           = (float*)d_out;

    const int n_edges = in_sizes[1] / 32;          // E = 1,600,000
    const int grid    = (n_edges + TILE_M - 1) / TILE_M;

    cudaFuncSetAttribute(edgeblock_kernel,
                         cudaFuncAttributeMaxDynamicSharedMemorySize, SMEM_BYTES);
    edgeblock_kernel<<<grid, NTHREADS, SMEM_BYTES>>>(
        nodes, edges, graph_globals, send, recv, batch_edges,
        W1, b1, W2, b2, out);
}

// round 7
// speedup vs baseline: 2.3998x; 1.5978x over previous
#include <cuda_runtime.h>
#include <cstdint>

// EdgeBlock fused MLP, TF32 mma.sync. Round 6:
//  - weights pre-packed (prep kernel) into fragment-ordered tf32 float2 in
//    __device__ scratch -> one coalesced LDG.64 per B-fragment, no weight smem
//  - smem = x tile only (61KB) -> 3 CTAs/SM; launch_bounds(256,3) caps regs
// x = [edges(32) | nodes[send](32) | nodes[recv](32) | globals[batch](16)]  (K=112)
// h = relu(x @ W1 + b1) (64);  y = h @ W2 + b2 (32)

#define TILE_M 128
#define NTHREADS 256

#define SX_STRIDE 116       // 112 + pad -> conflict-free fragment LDS
#define SH_STRIDE 68        // 64 + pad
#define OFF_X     0                       // 128*116 = 14848 floats
#define OFF_IDX   14848                   // 3*128 ints
#define SMEM_FLOATS (14848 + 384)
#define SMEM_BYTES  (SMEM_FLOATS * 4)     // 60928

// fragment-packed weights: W1P[(ks*8+nt)*32 + lane] = (b0,b1) for that mma
__device__ float2 d_W1P[14 * 8 * 32];     // 28672 B
__device__ float2 d_W2P[8 * 4 * 32];      // 8192 B

__device__ __forceinline__ float tf32_rna(float x) {
    unsigned u;
    asm("cvt.rna.tf32.f32 %0, %1;" : "=r"(u) : "f"(x));
    return __uint_as_float(u);
}

__device__ __forceinline__ void mma_tf32_16x8x8(float* c, const unsigned* a,
                                                unsigned b0, unsigned b1) {
    asm volatile(
        "mma.sync.aligned.m16n8k8.row.col.f32.tf32.tf32.f32 "
        "{%0,%1,%2,%3}, {%4,%5,%6,%7}, {%8,%9}, {%0,%1,%2,%3};"
        : "+f"(c[0]), "+f"(c[1]), "+f"(c[2]), "+f"(c[3])
        : "r"(a[0]), "r"(a[1]), "r"(a[2]), "r"(a[3]), "r"(b0), "r"(b1));
}

__global__ void prep_weights(const float* __restrict__ W1,
                             const float* __restrict__ W2) {
    int i = blockIdx.x * blockDim.x + threadIdx.x;
    if (i < 14 * 8 * 32) {
        int lane = i & 31, nt = (i >> 5) & 7, ks = i >> 8;
        int g = lane >> 2, c = lane & 3;
        float b0 = W1[(ks * 8 + c) * 64 + nt * 8 + g];
        float b1 = W1[(ks * 8 + c + 4) * 64 + nt * 8 + g];
        d_W1P[i] = make_float2(tf32_rna(b0), tf32_rna(b1));
    }
    if (i < 8 * 4 * 32) {
        int lane = i & 31, nt = (i >> 5) & 3, ks = i >> 7;
        int g = lane >> 2, c = lane & 3;
        float b0 = W2[(ks * 8 + c) * 32 + nt * 8 + g];
        float b1 = W2[(ks * 8 + c + 4) * 32 + nt * 8 + g];
        d_W2P[i] = make_float2(tf32_rna(b0), tf32_rna(b1));
    }
}

__global__ void __launch_bounds__(NTHREADS, 3)
edgeblock_kernel(const float* __restrict__ nodes,
                 const float* __restrict__ edges,
                 const float* __restrict__ graph_globals,
                 const int*   __restrict__ send,
                 const int*   __restrict__ recv,
                 const int*   __restrict__ batch_edges,
                 const float* __restrict__ b1,
                 const float* __restrict__ b2,
                 float*       __restrict__ out) {
    extern __shared__ float sm[];
    float* sX   = sm + OFF_X;            // [128][116] tf32 (aliased by sH)
    int*   sIdx = (int*)(sm + OFF_IDX);  // send[128] | recv[128] | batch[128]

    const int t  = threadIdx.x;
    const int e0 = blockIdx.x * TILE_M;

    if (t < 128) {
        int e = e0 + t;
        sIdx[t]       = send[e];
        sIdx[128 + t] = recv[e];
        sIdx[256 + t] = batch_edges[e];
    }
    __syncthreads();

    // ---- stage x tile (coalesced float4 reads, tf32 convert) ----
    for (int i = t; i < TILE_M * 8; i += NTHREADS) {
        int e = i >> 3, seg = i & 7;
        float4 v = *reinterpret_cast<const float4*>(edges + (size_t)(e0 + e) * 32 + seg * 4);
        float* d = sX + e * SX_STRIDE + seg * 4;
        d[0] = tf32_rna(v.x); d[1] = tf32_rna(v.y);
        d[2] = tf32_rna(v.z); d[3] = tf32_rna(v.w);
    }
    for (int i = t; i < TILE_M * 8; i += NTHREADS) {
        int e = i >> 3, seg = i & 7;
        int n = sIdx[e];
        float4 v = *reinterpret_cast<const float4*>(nodes + (size_t)n * 32 + seg * 4);
        float* d = sX + e * SX_STRIDE + 32 + seg * 4;
        d[0] = tf32_rna(v.x); d[1] = tf32_rna(v.y);
        d[2] = tf32_rna(v.z); d[3] = tf32_rna(v.w);
    }
    for (int i = t; i < TILE_M * 8; i += NTHREADS) {
        int e = i >> 3, seg = i & 7;
        int n = sIdx[128 + e];
        float4 v = *reinterpret_cast<const float4*>(nodes + (size_t)n * 32 + seg * 4);
        float* d = sX + e * SX_STRIDE + 64 + seg * 4;
        d[0] = tf32_rna(v.x); d[1] = tf32_rna(v.y);
        d[2] = tf32_rna(v.z); d[3] = tf32_rna(v.w);
    }
    for (int i = t; i < TILE_M * 4; i += NTHREADS) {
        int e = i >> 2, seg = i & 3;
        int g = sIdx[256 + e];
        float4 v = *reinterpret_cast<const float4*>(graph_globals + (size_t)g * 16 + seg * 4);
        float* d = sX + e * SX_STRIDE + 96 + seg * 4;
        d[0] = tf32_rna(v.x); d[1] = tf32_rna(v.y);
        d[2] = tf32_rna(v.z); d[3] = tf32_rna(v.w);
    }
    __syncthreads();

    // ---- layer 1: [128,112] @ [112,64]; warp w owns rows [w*16, w*16+16) ----
    const int lane = t & 31;
    const int w    = t >> 5;
    const int g    = lane >> 2;
    const int c    = lane & 3;
    const int r    = w * 16 + g;

    const float2* w1p = d_W1P + lane;   // + (ks*8+nt)*32
    const float2* w2p = d_W2P + lane;   // + (ks*4+nt)*32

    float acc[8][4];
#pragma unroll
    for (int nt = 0; nt < 8; nt++)
#pragma unroll
        for (int q = 0; q < 4; q++) acc[nt][q] = 0.0f;

#pragma unroll
    for (int ks = 0; ks < 14; ks++) {
        const int k = ks * 8;
        unsigned a[4];
        a[0] = __float_as_uint(sX[r * SX_STRIDE + k + c]);
        a[1] = __float_as_uint(sX[(r + 8) * SX_STRIDE + k + c]);
        a[2] = __float_as_uint(sX[r * SX_STRIDE + k + c + 4]);
        a[3] = __float_as_uint(sX[(r + 8) * SX_STRIDE + k + c + 4]);
#pragma unroll
        for (int nt = 0; nt < 8; nt++) {
            float2 b = __ldg(w1p + (ks * 8 + nt) * 32);
            mma_tf32_16x8x8(acc[nt], a, __float_as_uint(b.x), __float_as_uint(b.y));
        }
    }
    __syncthreads();   // done reading sX; sH aliases it

    // ---- bias + relu + tf32 -> smem h ----
    float* sH = sm + OFF_X;   // [128][68]
#pragma unroll
    for (int nt = 0; nt < 8; nt++) {
        int col = nt * 8 + 2 * c;
        float bb0 = __ldg(b1 + col), bb1 = __ldg(b1 + col + 1);
        float h0 = fmaxf(acc[nt][0] + bb0, 0.0f);
        float h1 = fmaxf(acc[nt][1] + bb1, 0.0f);
        float h2 = fmaxf(acc[nt][2] + bb0, 0.0f);
        float h3 = fmaxf(acc[nt][3] + bb1, 0.0f);
        sH[r * SH_STRIDE + col]           = tf32_rna(h0);
        sH[r * SH_STRIDE + col + 1]       = tf32_rna(h1);
        sH[(r + 8) * SH_STRIDE + col]     = tf32_rna(h2);
        sH[(r + 8) * SH_STRIDE + col + 1] = tf32_rna(h3);
    }
    __syncthreads();

    // ---- layer 2: [128,64] @ [64,32] ----
    float d2[4][4];
#pragma unroll
    for (int nt = 0; nt < 4; nt++)
#pragma unroll
        for (int q = 0; q < 4; q++) d2[nt][q] = 0.0f;

#pragma unroll
    for (int ks = 0; ks < 8; ks++) {
        const int k = ks * 8;
        unsigned a[4];
        a[0] = __float_as_uint(sH[r * SH_STRIDE + k + c]);
        a[1] = __float_as_uint(sH[(r + 8) * SH_STRIDE + k + c]);
        a[2] = __float_as_uint(sH[r * SH_STRIDE + k + c + 4]);
        a[3] = __float_as_uint(sH[(r + 8) * SH_STRIDE + k + c + 4]);
#pragma unroll
        for (int nt = 0; nt < 4; nt++) {
            float2 b = __ldg(w2p + (ks * 4 + nt) * 32);
            mma_tf32_16x8x8(d2[nt], a, __float_as_uint(b.x), __float_as_uint(b.y));
        }
    }

    // ---- epilogue: bias + store out[E,32] ----
#pragma unroll
    for (int nt = 0; nt < 4; nt++) {
        int col = nt * 8 + 2 * c;
        float bb0 = __ldg(b2 + col), bb1 = __ldg(b2 + col + 1);
        float2 v0 = make_float2(d2[nt][0] + bb0, d2[nt][1] + bb1);
        float2 v1 = make_float2(d2[nt][2] + bb0, d2[nt][3] + bb1);
        *reinterpret_cast<float2*>(out + (size_t)(e0 + r) * 32 + col)     = v0;
        *reinterpret_cast<float2*>(out + (size_t)(e0 + r + 8) * 32 + col) = v1;
    }
}

extern "C" void kernel_launch(void* const* d_in, const int* in_sizes, int n_in,
                              void* d_out, int out_size) {
    const float* nodes         = (const float*)d_in[0];
    const float* edges         = (const float*)d_in[1];
    const float* graph_globals = (const float*)d_in[2];
    const int*   send          = (const int*)d_in[3];
    const int*   recv          = (const int*)d_in[4];
    const int*   batch_edges   = (const int*)d_in[5];
    const float* W1            = (const float*)d_in[6];
    const float* b1            = (const float*)d_in[7];
    const float* W2            = (const float*)d_in[8];
    const float* b2            = (const float*)d_in[9];
    float*       out           = (float*)d_out;

    const int n_edges = in_sizes[1] / 32;          // 1,600,000
    const int grid    = (n_edges + TILE_M - 1) / TILE_M;

    prep_weights<<<(14 * 8 * 32 + 255) / 256, 256>>>(W1, W2);

    cudaFuncSetAttribute(edgeblock_kernel,
                         cudaFuncAttributeMaxDynamicSharedMemorySize, SMEM_BYTES);
    edgeblock_kernel<<<grid, NTHREADS, SMEM_BYTES>>>(
        nodes, edges, graph_globals, send, recv, batch_edges,
        b1, b2, out);
}